// round 1
// baseline (speedup 1.0000x reference)
#include <cuda_runtime.h>

// ---------------------------------------------------------------------------
// Problem constants
// ---------------------------------------------------------------------------
static constexpr int HH    = 128;
static constexpr int WWI   = 128;
static constexpr int L     = HH * WWI;      // 16384
static constexpr int BATCH = 2;
static constexpr int DIM   = 128;
static constexpr int NPIX  = BATCH * L;     // 32768
static constexpr int HEADS = 4;
static constexpr int HD    = 32;
static constexpr float ATTN_SCALE = 0.17677669529663687f; // 32^-0.5
static constexpr float BN_EPS = 1e-5f;

// ---------------------------------------------------------------------------
// Scratch (static device globals; no allocation anywhere)
// ---------------------------------------------------------------------------
__device__ float g_xt  [NPIX * 32];     // x  transposed (B,HW,32)
__device__ float g_b1  [NPIX * DIM];
__device__ float g_b2  [NPIX * DIM];
__device__ float g_v   [NPIX * DIM];
__device__ float g_pre [NPIX * DIM];
__device__ float g_attn[NPIX * 324];
__device__ float g_wt1 [32  * 9 * DIM]; // conv weights transposed [ci][rs][co]
__device__ float g_wt2 [DIM * 9 * DIM];
__device__ float g_wt3 [DIM * 9 * DIM];
__device__ float g_wt4 [DIM * 9 * DIM];

// ---------------------------------------------------------------------------
// Weight reorg: w[co][ci][r][s] (OIHW) -> wt[ci][r][s][co]
// ---------------------------------------------------------------------------
__global__ void wtrans_kernel(const float* __restrict__ w, float* __restrict__ wt, int cin) {
    int idx = blockIdx.x * 256 + threadIdx.x;
    int total = cin * 9 * DIM;
    if (idx >= total) return;
    int co = idx & (DIM - 1);
    int t  = idx >> 7;        // ci*9 + rs
    int rs = t % 9;
    int ci = t / 9;
    wt[idx] = w[(co * cin + ci) * 9 + rs];
}

// ---------------------------------------------------------------------------
// Batched 2D transpose: in (B,R,C) -> out (B,C,R)
// ---------------------------------------------------------------------------
__global__ void transpose_bat(const float* __restrict__ in, float* __restrict__ out,
                              int R, int C) {
    __shared__ float tile[32][33];
    int b = blockIdx.z;
    const float* ip = in  + (size_t)b * R * C;
    float*       op = out + (size_t)b * R * C;
    int c0 = blockIdx.x * 32, r0 = blockIdx.y * 32;
    int tx = threadIdx.x, ty = threadIdx.y;
    #pragma unroll
    for (int i = 0; i < 32; i += 8) {
        int r = r0 + ty + i, c = c0 + tx;
        if (r < R && c < C) tile[ty + i][tx] = ip[(size_t)r * C + c];
    }
    __syncthreads();
    #pragma unroll
    for (int i = 0; i < 32; i += 8) {
        int c = c0 + ty + i, r = r0 + tx;
        if (r < R && c < C) op[(size_t)c * R + r] = tile[tx][ty + i];
    }
}

// ---------------------------------------------------------------------------
// Conv3x3 (pad 1) + BatchNorm(eval) + TeLU, channel-last.
//   in  : (B,H,W,CIN)
//   wt  : (CIN,3,3,128)  [pre-transposed]
//   out : (B,H,W,128)
// Block: one row y, 64 cols, all 128 couts. 256 thr: thread = 8 co x 4 px.
// ---------------------------------------------------------------------------
template <int CIN>
__global__ __launch_bounds__(256) void conv3x3_bn_telu(
    const float* __restrict__ in, const float* __restrict__ wt,
    const float* __restrict__ bn_g, const float* __restrict__ bn_b,
    const float* __restrict__ bn_m, const float* __restrict__ bn_v,
    float* __restrict__ out)
{
    constexpr int CK = 8;
    __shared__ __align__(16) float ws[CK * 9 * DIM];   // [ci][r][s][co]
    __shared__ __align__(16) float ins[CK][3][68];     // [ci][r][col], col = x-x0+1

    const int tid = threadIdx.x;
    const int x0  = blockIdx.x * 64;
    const int y   = blockIdx.y;
    const int b   = blockIdx.z;

    const int ct  = tid >> 4;       // 0..15
    const int pt  = tid & 15;       // 0..15
    const int co0 = ct * 8;
    const int px0 = pt * 4;

    float acc[8][4];
    #pragma unroll
    for (int c = 0; c < 8; c++)
        #pragma unroll
        for (int k = 0; k < 4; k++) acc[c][k] = 0.f;

    for (int ci0 = 0; ci0 < CIN; ci0 += CK) {
        __syncthreads();
        // stage weights chunk (contiguous slice of wt)
        for (int idx = tid; idx < CK * 9 * DIM; idx += 256)
            ws[idx] = wt[ci0 * 9 * DIM + idx];
        // stage input rows y-1..y+1, cols x0-1..x0+64
        for (int idx = tid; idx < CK * 3 * 66; idx += 256) {
            int ci = idx & 7;
            int t  = idx >> 3;
            int col = t % 66;
            int r   = t / 66;
            int yy = y + r - 1;
            int xx = x0 + col - 1;
            float val = 0.f;
            if (yy >= 0 && yy < HH && xx >= 0 && xx < WWI)
                val = in[(((size_t)(b * HH + yy) * WWI) + xx) * CIN + ci0 + ci];
            ins[ci][r][col] = val;
        }
        __syncthreads();

        #pragma unroll
        for (int ci = 0; ci < CK; ci++) {
            #pragma unroll
            for (int r = 0; r < 3; r++) {
                float iv[6];
                #pragma unroll
                for (int j = 0; j < 6; j++) iv[j] = ins[ci][r][px0 + j];
                #pragma unroll
                for (int s = 0; s < 3; s++) {
                    const float4* wp = (const float4*)&ws[(ci * 9 + r * 3 + s) * DIM + co0];
                    float4 w0 = wp[0], w1 = wp[1];
                    float wv[8] = {w0.x, w0.y, w0.z, w0.w, w1.x, w1.y, w1.z, w1.w};
                    #pragma unroll
                    for (int c = 0; c < 8; c++)
                        #pragma unroll
                        for (int k = 0; k < 4; k++)
                            acc[c][k] += wv[c] * iv[k + s];
                }
            }
        }
    }

    // BN + TeLU epilogue
    float sc[8], sh[8];
    #pragma unroll
    for (int c = 0; c < 8; c++) {
        int co = co0 + c;
        float s = bn_g[co] * rsqrtf(bn_v[co] + BN_EPS);
        sc[c] = s;
        sh[c] = bn_b[co] - bn_m[co] * s;
    }
    #pragma unroll
    for (int k = 0; k < 4; k++) {
        float o[8];
        #pragma unroll
        for (int c = 0; c < 8; c++) {
            float yv = acc[c][k] * sc[c] + sh[c];
            o[c] = yv * tanhf(expf(yv));
        }
        float* op = out + (((size_t)(b * HH + y) * WWI) + x0 + px0 + k) * DIM + co0;
        ((float4*)op)[0] = make_float4(o[0], o[1], o[2], o[3]);
        ((float4*)op)[1] = make_float4(o[4], o[5], o[6], o[7]);
    }
}

// ---------------------------------------------------------------------------
// Generic linear: out[m,n] = sum_k in[m,k]*w[n,k] + b[n], K = 128.
// Block: 32 px x 128 co-tile; 128 thr, thread = 4 co x 8 px.
// grid = (M/32, ceil(N/128))
// ---------------------------------------------------------------------------
__global__ __launch_bounds__(128) void linear_kernel(
    const float* __restrict__ in, const float* __restrict__ w,
    const float* __restrict__ bias, float* __restrict__ out, int N)
{
    __shared__ __align__(16) float xs[32][132];
    const int m0 = blockIdx.x * 32;
    const int tid = threadIdx.x;
    for (int idx = tid; idx < 32 * 128; idx += 128) {
        int m = idx >> 7, k = idx & 127;
        xs[m][k] = in[(size_t)(m0 + m) * 128 + k];
    }
    __syncthreads();

    const int pt  = tid & 3;               // pixels pt, pt+4, ..., pt+28
    const int ct  = tid >> 2;              // 0..31
    const int co0 = blockIdx.y * 128 + ct * 4;

    bool valid[4];
    #pragma unroll
    for (int c = 0; c < 4; c++) valid[c] = (co0 + c) < N;

    float acc[4][8];
    #pragma unroll
    for (int c = 0; c < 4; c++)
        #pragma unroll
        for (int i = 0; i < 8; i++) acc[c][i] = 0.f;

    for (int k4 = 0; k4 < 128; k4 += 4) {
        float4 wq[4];
        #pragma unroll
        for (int c = 0; c < 4; c++)
            wq[c] = valid[c] ? *(const float4*)(w + (size_t)(co0 + c) * 128 + k4)
                             : make_float4(0.f, 0.f, 0.f, 0.f);
        #pragma unroll
        for (int i = 0; i < 8; i++) {
            float4 xq = *(const float4*)&xs[pt + 4 * i][k4];
            #pragma unroll
            for (int c = 0; c < 4; c++)
                acc[c][i] += xq.x * wq[c].x + xq.y * wq[c].y
                           + xq.z * wq[c].z + xq.w * wq[c].w;
        }
    }
    #pragma unroll
    for (int c = 0; c < 4; c++) {
        if (!valid[c]) continue;
        float bb = bias[co0 + c];
        #pragma unroll
        for (int i = 0; i < 8; i++)
            out[(size_t)(m0 + pt + 4 * i) * N + co0 + c] = acc[c][i] + bb;
    }
}

// ---------------------------------------------------------------------------
// Scaled softmax over groups of 9 (in place)
// ---------------------------------------------------------------------------
__global__ void softmax9_kernel(float* __restrict__ a, int rows) {
    int r = blockIdx.x * 256 + threadIdx.x;
    if (r >= rows) return;
    float* p = a + (size_t)r * 9;
    float v[9], mx = -1e30f;
    #pragma unroll
    for (int i = 0; i < 9; i++) { v[i] = p[i] * ATTN_SCALE; mx = fmaxf(mx, v[i]); }
    float s = 0.f;
    #pragma unroll
    for (int i = 0; i < 9; i++) { v[i] = expf(v[i] - mx); s += v[i]; }
    float inv = 1.f / s;
    #pragma unroll
    for (int i = 0; i < 9; i++) p[i] = v[i] * inv;
}

// ---------------------------------------------------------------------------
// Fused attention-apply + fold:
//   out[m, h*32+d] = sum_{dy,dx in 5x5} Wd[m,h,dy,dx] * v[m+(dy-2,dx-2), h*32+d]
//   Wd[m,h,δ]      = sum_{p: m-off_p in range, q-p = δ} attn[m-off_p, h, p, q]
// Tile: 8 rows x 16 cols, 128 thr (1 px each), loop heads.
// ---------------------------------------------------------------------------
__global__ __launch_bounds__(128) void apply_fold_kernel(
    const float* __restrict__ attn,   // (B, L, 4, 81)
    const float* __restrict__ v,      // (B,H,W,128)
    float* __restrict__ out)          // (B,H,W,128)
{
    __shared__ __align__(16) float vs[12 * 20 * 36];  // [row][col][c], padded stride 36

    const int tid = threadIdx.x;
    const int x0  = blockIdx.x * 16;
    const int y0  = blockIdx.y * 8;
    const int b   = blockIdx.z;
    const int ty  = tid >> 4, tx = tid & 15;
    const int y = y0 + ty, x = x0 + tx;

    for (int h = 0; h < HEADS; h++) {
        __syncthreads();
        // stage v tile (rows y0-2..y0+9, cols x0-2..x0+17), head channel slice
        for (int idx = tid; idx < 12 * 20 * 32; idx += 128) {
            int c   = idx & 31;
            int t   = idx >> 5;
            int col = t % 20, row = t / 20;
            int yy = y0 + row - 2, xx = x0 + col - 2;
            float val = 0.f;
            if (yy >= 0 && yy < HH && xx >= 0 && xx < WWI)
                val = v[(((size_t)(b * HH + yy) * WWI) + xx) * DIM + h * HD + c];
            vs[(row * 20 + col) * 36 + c] = val;
        }
        __syncthreads();

        // phase A: per-pixel 5x5 delta weights from 3x3x(3x3) attention
        float Wd[25];
        #pragma unroll
        for (int d = 0; d < 25; d++) Wd[d] = 0.f;
        #pragma unroll
        for (int pi = 0; pi < 3; pi++)
            #pragma unroll
            for (int pj = 0; pj < 3; pj++) {
                int ly = y - (pi - 1), lx = x - (pj - 1);
                if (ly < 0 || ly >= HH || lx < 0 || lx >= WWI) continue;
                const float* ap = attn
                    + ((size_t)((b * L + ly * WWI + lx) * HEADS + h)) * 81
                    + (pi * 3 + pj) * 9;
                #pragma unroll
                for (int qi = 0; qi < 3; qi++)
                    #pragma unroll
                    for (int qj = 0; qj < 3; qj++)
                        Wd[(qi - pi + 2) * 5 + (qj - pj + 2)] += ap[qi * 3 + qj];
            }

        // phase B: 5x5 gather over v
        float acc[HD];
        #pragma unroll
        for (int d = 0; d < HD; d++) acc[d] = 0.f;
        #pragma unroll
        for (int dy = 0; dy < 5; dy++)
            #pragma unroll
            for (int dx = 0; dx < 5; dx++) {
                float wv = Wd[dy * 5 + dx];
                const float4* vp = (const float4*)&vs[((ty + dy) * 20 + (tx + dx)) * 36];
                #pragma unroll
                for (int q = 0; q < 8; q++) {
                    float4 vq = vp[q];
                    acc[q * 4 + 0] += wv * vq.x;
                    acc[q * 4 + 1] += wv * vq.y;
                    acc[q * 4 + 2] += wv * vq.z;
                    acc[q * 4 + 3] += wv * vq.w;
                }
            }

        float4* op = (float4*)&out[(((size_t)(b * HH + y) * WWI) + x) * DIM + h * HD];
        #pragma unroll
        for (int q = 0; q < 8; q++)
            op[q] = make_float4(acc[q*4], acc[q*4+1], acc[q*4+2], acc[q*4+3]);
    }
}

// ---------------------------------------------------------------------------
// Launch
// ---------------------------------------------------------------------------
extern "C" void kernel_launch(void* const* d_in, const int* in_sizes, int n_in,
                              void* d_out, int out_size) {
    const float* x    = (const float*)d_in[0];
    const float* fg   = (const float*)d_in[1];
    const float* bg   = (const float*)d_in[2];
    const float* w1   = (const float*)d_in[3];
    const float* w2   = (const float*)d_in[4];
    const float* w3   = (const float*)d_in[5];
    const float* w4   = (const float*)d_in[6];
    const float* bng  = (const float*)d_in[7];
    const float* bnb  = (const float*)d_in[8];
    const float* bnm  = (const float*)d_in[9];
    const float* bnv  = (const float*)d_in[10];
    const float* vw   = (const float*)d_in[11];
    const float* vb   = (const float*)d_in[12];
    const float* afgw = (const float*)d_in[13];
    const float* afgb = (const float*)d_in[14];
    const float* abgw = (const float*)d_in[15];
    const float* abgb = (const float*)d_in[16];
    const float* pw   = (const float*)d_in[17];
    const float* pb   = (const float*)d_in[18];
    float* out = (float*)d_out;

    float *xt, *b1, *b2, *vbuf, *pre, *attn, *wt1, *wt2, *wt3, *wt4;
    cudaGetSymbolAddress((void**)&xt,   g_xt);
    cudaGetSymbolAddress((void**)&b1,   g_b1);
    cudaGetSymbolAddress((void**)&b2,   g_b2);
    cudaGetSymbolAddress((void**)&vbuf, g_v);
    cudaGetSymbolAddress((void**)&pre,  g_pre);
    cudaGetSymbolAddress((void**)&attn, g_attn);
    cudaGetSymbolAddress((void**)&wt1,  g_wt1);
    cudaGetSymbolAddress((void**)&wt2,  g_wt2);
    cudaGetSymbolAddress((void**)&wt3,  g_wt3);
    cudaGetSymbolAddress((void**)&wt4,  g_wt4);

    const dim3 convGrid(2, HH, BATCH);
    const int smRows = NPIX * HEADS * 9;           // 1179648 softmax rows

    // weight reorg
    wtrans_kernel<<<(32  * 9 * DIM + 255) / 256, 256>>>(w1, wt1, 32);
    wtrans_kernel<<<(DIM * 9 * DIM + 255) / 256, 256>>>(w2, wt2, DIM);
    wtrans_kernel<<<(DIM * 9 * DIM + 255) / 256, 256>>>(w3, wt3, DIM);
    wtrans_kernel<<<(DIM * 9 * DIM + 255) / 256, 256>>>(w4, wt4, DIM);

    // input_cbt
    transpose_bat<<<dim3(L / 32, 1, BATCH), dim3(32, 8)>>>(x, xt, 32, L);
    conv3x3_bn_telu<32> <<<convGrid, 256>>>(xt, wt1, bng,       bnb,       bnm,       bnv,       b1);
    conv3x3_bn_telu<128><<<convGrid, 256>>>(b1, wt2, bng + 128, bnb + 128, bnm + 128, bnv + 128, b2);

    // v projection
    linear_kernel<<<dim3(NPIX / 32, 1), 128>>>(b2, vw, vb, vbuf, 128);

    // fg attention pass
    transpose_bat<<<dim3(L / 32, 4, BATCH), dim3(32, 8)>>>(fg, b1, DIM, L);
    linear_kernel<<<dim3(NPIX / 32, 3), 128>>>(b1, afgw, afgb, attn, 324);
    softmax9_kernel<<<(smRows + 255) / 256, 256>>>(attn, smRows);
    apply_fold_kernel<<<dim3(WWI / 16, HH / 8, BATCH), 128>>>(attn, vbuf, pre);
    linear_kernel<<<dim3(NPIX / 32, 1), 128>>>(pre, pw, pb, b2, 128);   // xw_fg (NHWC)

    // bg attention pass (values = xw_fg)
    transpose_bat<<<dim3(L / 32, 4, BATCH), dim3(32, 8)>>>(bg, b1, DIM, L);
    linear_kernel<<<dim3(NPIX / 32, 3), 128>>>(b1, abgw, abgb, attn, 324);
    softmax9_kernel<<<(smRows + 255) / 256, 256>>>(attn, smRows);
    apply_fold_kernel<<<dim3(WWI / 16, HH / 8, BATCH), 128>>>(attn, b2, pre);
    linear_kernel<<<dim3(NPIX / 32, 1), 128>>>(pre, pw, pb, b1, 128);   // xw_bg (NHWC)

    // output_cbt
    conv3x3_bn_telu<128><<<convGrid, 256>>>(b1, wt3, bng + 256, bnb + 256, bnm + 256, bnv + 256, b2);
    conv3x3_bn_telu<128><<<convGrid, 256>>>(b2, wt4, bng + 384, bnb + 384, bnm + 384, bnv + 384, pre);

    // NHWC -> NCHW output
    transpose_bat<<<dim3(DIM / 32, L / 32, BATCH), dim3(32, 8)>>>(pre, out, L, DIM);
}

// round 4
// speedup vs baseline: 1.5379x; 1.5379x over previous
#include <cuda_runtime.h>
#include <cuda_bf16.h>
#include <cstdint>

// ---------------------------------------------------------------------------
// Problem constants
// ---------------------------------------------------------------------------
static constexpr int HH    = 128;
static constexpr int WWI   = 128;
static constexpr int L     = HH * WWI;      // 16384
static constexpr int BATCH = 2;
static constexpr int DIM   = 128;
static constexpr int NPIX  = BATCH * L;     // 32768
static constexpr int HEADS = 4;
static constexpr int HD    = 32;
static constexpr float ATTN_SCALE = 0.17677669529663687f; // 32^-0.5
static constexpr float BN_EPS = 1e-5f;

// mma_conv shared-memory layout (bytes)
static constexpr int A_OFF   = 1024;                 // after BN luts
static constexpr int A_RSTR  = 132 * 32;             // 4224 per r-row
static constexpr int A_SSTR  = 3 * A_RSTR;           // 12672 per split
static constexpr int B_OFF   = A_OFF + 2 * A_SSTR;   // 26368
static constexpr int B_BYTES = 9 * 2 * 128 * 32;     // 73728
static constexpr int CONV_SMEM = B_OFF + B_BYTES;    // 100096

// ---------------------------------------------------------------------------
// Scratch (static device globals; no allocation anywhere)
// ---------------------------------------------------------------------------
__device__ float g_xt  [NPIX * 32];      // x transposed (B,HW,32) fp32
__device__ float g_b1  [NPIX * DIM];
__device__ float g_b2  [NPIX * DIM];
__device__ float g_v   [NPIX * DIM];
__device__ float g_pre [NPIX * DIM];
__device__ float g_attn[NPIX * 324];

__device__ __nv_bfloat16 g_c1h[NPIX * 32];   // conv1 input hi/lo (32 ch)
__device__ __nv_bfloat16 g_c1l[NPIX * 32];
__device__ __nv_bfloat16 g_Ph [NPIX * DIM];  // ping bf16 pair (128 ch)
__device__ __nv_bfloat16 g_Pl [NPIX * DIM];
__device__ __nv_bfloat16 g_Qh [NPIX * DIM];  // pong bf16 pair (128 ch)
__device__ __nv_bfloat16 g_Ql [NPIX * DIM];

// ldmatrix-ready conv weights: [kc][tap][split][n(128)][k16], 16B-XOR swizzled
__device__ __nv_bfloat16 g_wB1[2 * 9 * 2 * 128 * 16];   // CIN=32
__device__ __nv_bfloat16 g_wB2[8 * 9 * 2 * 128 * 16];   // CIN=128
__device__ __nv_bfloat16 g_wB3[8 * 9 * 2 * 128 * 16];
__device__ __nv_bfloat16 g_wB4[8 * 9 * 2 * 128 * 16];

// ---------------------------------------------------------------------------
// Helpers: ldmatrix + bf16 mma (sm_80-era instructions; compile at compute_100)
// ---------------------------------------------------------------------------
__device__ __forceinline__ uint32_t smem_u32(const void* p) {
    uint32_t a;
    asm("{ .reg .u64 t; cvta.to.shared.u64 t, %1; cvt.u32.u64 %0, t; }"
        : "=r"(a) : "l"(p));
    return a;
}

__device__ __forceinline__ void ldsm4(uint32_t addr, uint32_t& r0, uint32_t& r1,
                                      uint32_t& r2, uint32_t& r3) {
    asm volatile("ldmatrix.sync.aligned.m8n8.x4.shared.b16 {%0,%1,%2,%3}, [%4];"
                 : "=r"(r0), "=r"(r1), "=r"(r2), "=r"(r3) : "r"(addr));
}

__device__ __forceinline__ void mma16816(float* d, const uint32_t* a, const uint32_t* b) {
    asm volatile(
        "mma.sync.aligned.m16n8k16.row.col.f32.bf16.bf16.f32 "
        "{%0,%1,%2,%3}, {%4,%5,%6,%7}, {%8,%9}, {%0,%1,%2,%3};"
        : "+f"(d[0]), "+f"(d[1]), "+f"(d[2]), "+f"(d[3])
        : "r"(a[0]), "r"(a[1]), "r"(a[2]), "r"(a[3]), "r"(b[0]), "r"(b[1]));
}

// ---------------------------------------------------------------------------
// Conv weight prep: OIHW fp32 -> split-bf16 in ldmatrix layout
//   byte offset = (kc*9 + tap)*8192 + split*4096 + n*32 + ((kh^((n>>2)&1))<<4) + ki*2
// ---------------------------------------------------------------------------
__global__ void wprep_kernel(const float* __restrict__ w, __nv_bfloat16* __restrict__ wB,
                             int cin) {
    int nkc = cin >> 4;
    int total = nkc * 9 * 128 * 16;
    int idx = blockIdx.x * 256 + threadIdx.x;
    if (idx >= total) return;
    int k    = idx & 15;
    int n    = (idx >> 4) & 127;
    int rest = idx >> 11;
    int tap  = rest % 9;
    int kc   = rest / 9;
    int ci   = kc * 16 + k;
    float v = w[((size_t)n * cin + ci) * 9 + tap];
    __nv_bfloat16 hi = __float2bfloat16(v);
    __nv_bfloat16 lo = __float2bfloat16(v - __bfloat162float(hi));
    int kh = k >> 3, ki = k & 7;
    size_t base = ((size_t)kc * 9 + tap) * 8192;
    int off = n * 32 + ((kh ^ ((n >> 2) & 1)) << 4) + ki * 2;
    *(__nv_bfloat16*)((char*)wB + base + off)        = hi;
    *(__nv_bfloat16*)((char*)wB + base + 4096 + off) = lo;
}

// ---------------------------------------------------------------------------
// fp32 -> split-bf16 pair converter
// ---------------------------------------------------------------------------
__global__ void split_kernel(const float* __restrict__ in,
                             __nv_bfloat16* __restrict__ oh,
                             __nv_bfloat16* __restrict__ ol, int n) {
    int i = blockIdx.x * 256 + threadIdx.x;
    if (i >= n) return;
    float v = in[i];
    __nv_bfloat16 h = __float2bfloat16(v);
    oh[i] = h;
    ol[i] = __float2bfloat16(v - __bfloat162float(h));
}

// ---------------------------------------------------------------------------
// Tensor-core conv3x3 + BN + TeLU via mma.sync bf16, split-bf16 3-pass.
// Block = one image row: 128 px x 128 cout. 8 warps, each 32px x 64co.
// ---------------------------------------------------------------------------
template <int CIN, bool EMIT_F32, bool EMIT_BF16>
__global__ __launch_bounds__(256) void mma_conv(
    const __nv_bfloat16* __restrict__ in_hi, const __nv_bfloat16* __restrict__ in_lo,
    const __nv_bfloat16* __restrict__ wB,
    const float* __restrict__ bn_g, const float* __restrict__ bn_b,
    const float* __restrict__ bn_m, const float* __restrict__ bn_v,
    float* __restrict__ out_f32,
    __nv_bfloat16* __restrict__ out_hi, __nv_bfloat16* __restrict__ out_lo)
{
    extern __shared__ __align__(128) char smem[];
    constexpr int NKC = CIN / 16;

    const int y    = blockIdx.x;
    const int b    = blockIdx.y;
    const int tid  = threadIdx.x;
    const int wid  = tid >> 5;
    const int lane = tid & 31;
    const uint32_t sbase = smem_u32(smem);

    float* scs = (float*)smem;
    float* shs = scs + 128;
    if (tid < 128) {
        float sc = bn_g[tid] * rsqrtf(bn_v[tid] + BN_EPS);
        scs[tid] = sc;
        shs[tid] = bn_b[tid] - bn_m[tid] * sc;
    }

    const int mi = (wid >> 1) * 32;       // warp m-base (pixels)
    const int nb = (wid & 1) * 64;        // warp n-base (couts)
    const int lr = lane & 7;
    const int lq = lane >> 3;             // ldmatrix quad 0..3

    float d[2][8][4];
    #pragma unroll
    for (int mt = 0; mt < 2; mt++)
        #pragma unroll
        for (int nt = 0; nt < 8; nt++)
            #pragma unroll
            for (int q = 0; q < 4; q++) d[mt][nt][q] = 0.f;

    for (int kc = 0; kc < NKC; kc++) {
        __syncthreads();
        // --- stage A: 2 splits x 3 rows x 130 slots x 2 k-halves (16B each) ---
        for (int e = tid; e < 1560; e += 256) {
            int kh   = e & 1;
            int t    = e >> 1;
            int slot = t % 130;
            int t2   = t / 130;
            int r    = t2 % 3;
            int sp   = t2 / 3;
            int px = slot - 1, yy = y + r - 1;
            uint4 v = make_uint4(0, 0, 0, 0);
            if (yy >= 0 && yy < HH && px >= 0 && px < WWI) {
                size_t gi = (((size_t)(b * HH + yy)) * WWI + px) * CIN + kc * 16 + kh * 8;
                v = *(const uint4*)((sp ? in_lo : in_hi) + gi);
            }
            *(uint4*)(smem + A_OFF + sp * A_SSTR + r * A_RSTR + slot * 32
                      + ((kh ^ ((slot >> 2) & 1)) << 4)) = v;
        }
        // --- stage B: straight copy of pre-packed 72KB slice ---
        {
            const uint4* src = (const uint4*)(wB + (size_t)kc * 36864);
            uint4* dst = (uint4*)(smem + B_OFF);
            for (int e = tid; e < 4608; e += 256) dst[e] = src[e];
        }
        __syncthreads();

        #pragma unroll
        for (int tap = 0; tap < 9; tap++) {
            const int r = tap / 3, s = tap - r * 3;
            // A fragments (hi, lo) for 2 m-tiles
            uint32_t ah[2][4], al[2][4];
            #pragma unroll
            for (int mt = 0; mt < 2; mt++) {
                int slot = mi + mt * 16 + (lq & 1) * 8 + lr + s;  // px + 1 folded in
                int khq = lq >> 1;
                uint32_t adr = sbase + A_OFF + r * A_RSTR + slot * 32
                               + ((khq ^ ((slot >> 2) & 1)) << 4);
                ldsm4(adr,          ah[mt][0], ah[mt][1], ah[mt][2], ah[mt][3]);
                ldsm4(adr + A_SSTR, al[mt][0], al[mt][1], al[mt][2], al[mt][3]);
            }
            // B fragments (hi, lo) for 8 n-tiles
            uint32_t bh[8][2], bl[8][2];
            #pragma unroll
            for (int np = 0; np < 4; np++) {
                int n_row = nb + np * 16 + (lq >> 1) * 8 + lr;
                int kh = lq & 1;
                uint32_t adr = sbase + B_OFF + tap * 8192 + n_row * 32
                               + ((kh ^ ((n_row >> 2) & 1)) << 4);
                ldsm4(adr,        bh[2*np][0], bh[2*np][1], bh[2*np+1][0], bh[2*np+1][1]);
                ldsm4(adr + 4096, bl[2*np][0], bl[2*np][1], bl[2*np+1][0], bl[2*np+1][1]);
            }
            #pragma unroll
            for (int mt = 0; mt < 2; mt++)
                #pragma unroll
                for (int nt = 0; nt < 8; nt++) {
                    mma16816(d[mt][nt], ah[mt], bh[nt]);
                    mma16816(d[mt][nt], ah[mt], bl[nt]);
                    mma16816(d[mt][nt], al[mt], bh[nt]);
                }
        }
    }

    // --- epilogue: BN + TeLU, write NHWC ---
    const int g = lane >> 2, t = lane & 3;
    #pragma unroll
    for (int mt = 0; mt < 2; mt++) {
        int px0 = mi + mt * 16 + g;
        size_t row0 = (((size_t)(b * HH + y)) * WWI + px0) * DIM;
        size_t row1 = row0 + 8 * DIM;
        #pragma unroll
        for (int nt = 0; nt < 8; nt++) {
            int col = nb + nt * 8 + t * 2;
            float s0 = scs[col], s1 = scs[col + 1];
            float h0 = shs[col], h1 = shs[col + 1];
            float y0 = d[mt][nt][0] * s0 + h0;
            float y1 = d[mt][nt][1] * s1 + h1;
            float y2 = d[mt][nt][2] * s0 + h0;
            float y3 = d[mt][nt][3] * s1 + h1;
            float o0 = y0 * tanhf(expf(y0));
            float o1 = y1 * tanhf(expf(y1));
            float o2 = y2 * tanhf(expf(y2));
            float o3 = y3 * tanhf(expf(y3));
            if (EMIT_F32) {
                *(float2*)(out_f32 + row0 + col) = make_float2(o0, o1);
                *(float2*)(out_f32 + row1 + col) = make_float2(o2, o3);
            }
            if (EMIT_BF16) {
                __nv_bfloat16 a0 = __float2bfloat16(o0), a1 = __float2bfloat16(o1);
                __nv_bfloat16 a2 = __float2bfloat16(o2), a3 = __float2bfloat16(o3);
                *(__nv_bfloat162*)(out_hi + row0 + col) = __nv_bfloat162(a0, a1);
                *(__nv_bfloat162*)(out_hi + row1 + col) = __nv_bfloat162(a2, a3);
                *(__nv_bfloat162*)(out_lo + row0 + col) = __nv_bfloat162(
                    __float2bfloat16(o0 - __bfloat162float(a0)),
                    __float2bfloat16(o1 - __bfloat162float(a1)));
                *(__nv_bfloat162*)(out_lo + row1 + col) = __nv_bfloat162(
                    __float2bfloat16(o2 - __bfloat162float(a2)),
                    __float2bfloat16(o3 - __bfloat162float(a3)));
            }
        }
    }
}

// ---------------------------------------------------------------------------
// Batched 2D transpose: in (B,R,C) -> out (B,C,R)
// ---------------------------------------------------------------------------
__global__ void transpose_bat(const float* __restrict__ in, float* __restrict__ out,
                              int R, int C) {
    __shared__ float tile[32][33];
    int b = blockIdx.z;
    const float* ip = in  + (size_t)b * R * C;
    float*       op = out + (size_t)b * R * C;
    int c0 = blockIdx.x * 32, r0 = blockIdx.y * 32;
    int tx = threadIdx.x, ty = threadIdx.y;
    #pragma unroll
    for (int i = 0; i < 32; i += 8) {
        int r = r0 + ty + i, c = c0 + tx;
        if (r < R && c < C) tile[ty + i][tx] = ip[(size_t)r * C + c];
    }
    __syncthreads();
    #pragma unroll
    for (int i = 0; i < 32; i += 8) {
        int c = c0 + ty + i, r = r0 + tx;
        if (r < R && c < C) op[(size_t)c * R + r] = tile[tx][ty + i];
    }
}

// ---------------------------------------------------------------------------
// Generic linear: out[m,n] = sum_k in[m,k]*w[n,k] + b[n], K = 128.
// ---------------------------------------------------------------------------
__global__ __launch_bounds__(128) void linear_kernel(
    const float* __restrict__ in, const float* __restrict__ w,
    const float* __restrict__ bias, float* __restrict__ out, int N)
{
    __shared__ __align__(16) float xs[32][132];
    const int m0 = blockIdx.x * 32;
    const int tid = threadIdx.x;
    for (int idx = tid; idx < 32 * 128; idx += 128) {
        int m = idx >> 7, k = idx & 127;
        xs[m][k] = in[(size_t)(m0 + m) * 128 + k];
    }
    __syncthreads();

    const int pt  = tid & 3;
    const int ct  = tid >> 2;
    const int co0 = blockIdx.y * 128 + ct * 4;

    bool valid[4];
    #pragma unroll
    for (int c = 0; c < 4; c++) valid[c] = (co0 + c) < N;

    float acc[4][8];
    #pragma unroll
    for (int c = 0; c < 4; c++)
        #pragma unroll
        for (int i = 0; i < 8; i++) acc[c][i] = 0.f;

    for (int k4 = 0; k4 < 128; k4 += 4) {
        float4 wq[4];
        #pragma unroll
        for (int c = 0; c < 4; c++)
            wq[c] = valid[c] ? *(const float4*)(w + (size_t)(co0 + c) * 128 + k4)
                             : make_float4(0.f, 0.f, 0.f, 0.f);
        #pragma unroll
        for (int i = 0; i < 8; i++) {
            float4 xq = *(const float4*)&xs[pt + 4 * i][k4];
            #pragma unroll
            for (int c = 0; c < 4; c++)
                acc[c][i] += xq.x * wq[c].x + xq.y * wq[c].y
                           + xq.z * wq[c].z + xq.w * wq[c].w;
        }
    }
    #pragma unroll
    for (int c = 0; c < 4; c++) {
        if (!valid[c]) continue;
        float bb = bias[co0 + c];
        #pragma unroll
        for (int i = 0; i < 8; i++)
            out[(size_t)(m0 + pt + 4 * i) * N + co0 + c] = acc[c][i] + bb;
    }
}

// ---------------------------------------------------------------------------
// Scaled softmax over groups of 9 (in place)
// ---------------------------------------------------------------------------
__global__ void softmax9_kernel(float* __restrict__ a, int rows) {
    int r = blockIdx.x * 256 + threadIdx.x;
    if (r >= rows) return;
    float* p = a + (size_t)r * 9;
    float v[9], mx = -1e30f;
    #pragma unroll
    for (int i = 0; i < 9; i++) { v[i] = p[i] * ATTN_SCALE; mx = fmaxf(mx, v[i]); }
    float s = 0.f;
    #pragma unroll
    for (int i = 0; i < 9; i++) { v[i] = expf(v[i] - mx); s += v[i]; }
    float inv = 1.f / s;
    #pragma unroll
    for (int i = 0; i < 9; i++) p[i] = v[i] * inv;
}

// ---------------------------------------------------------------------------
// Fused attention-apply + fold (5x5 gather reformulation)
// ---------------------------------------------------------------------------
__global__ __launch_bounds__(128) void apply_fold_kernel(
    const float* __restrict__ attn,   // (B, L, 4, 81)
    const float* __restrict__ v,      // (B,H,W,128)
    float* __restrict__ out)          // (B,H,W,128)
{
    __shared__ __align__(16) float vs[12 * 20 * 36];

    const int tid = threadIdx.x;
    const int x0  = blockIdx.x * 16;
    const int y0  = blockIdx.y * 8;
    const int b   = blockIdx.z;
    const int ty  = tid >> 4, tx = tid & 15;
    const int y = y0 + ty, x = x0 + tx;

    for (int h = 0; h < HEADS; h++) {
        __syncthreads();
        for (int idx = tid; idx < 12 * 20 * 32; idx += 128) {
            int c   = idx & 31;
            int t   = idx >> 5;
            int col = t % 20, row = t / 20;
            int yy = y0 + row - 2, xx = x0 + col - 2;
            float val = 0.f;
            if (yy >= 0 && yy < HH && xx >= 0 && xx < WWI)
                val = v[(((size_t)(b * HH + yy) * WWI) + xx) * DIM + h * HD + c];
            vs[(row * 20 + col) * 36 + c] = val;
        }
        __syncthreads();

        float Wd[25];
        #pragma unroll
        for (int d = 0; d < 25; d++) Wd[d] = 0.f;
        #pragma unroll
        for (int pi = 0; pi < 3; pi++)
            #pragma unroll
            for (int pj = 0; pj < 3; pj++) {
                int ly = y - (pi - 1), lx = x - (pj - 1);
                if (ly < 0 || ly >= HH || lx < 0 || lx >= WWI) continue;
                const float* ap = attn
                    + ((size_t)((b * L + ly * WWI + lx) * HEADS + h)) * 81
                    + (pi * 3 + pj) * 9;
                #pragma unroll
                for (int qi = 0; qi < 3; qi++)
                    #pragma unroll
                    for (int qj = 0; qj < 3; qj++)
                        Wd[(qi - pi + 2) * 5 + (qj - pj + 2)] += ap[qi * 3 + qj];
            }

        float acc[HD];
        #pragma unroll
        for (int d = 0; d < HD; d++) acc[d] = 0.f;
        #pragma unroll
        for (int dy = 0; dy < 5; dy++)
            #pragma unroll
            for (int dx = 0; dx < 5; dx++) {
                float wv = Wd[dy * 5 + dx];
                const float4* vp = (const float4*)&vs[((ty + dy) * 20 + (tx + dx)) * 36];
                #pragma unroll
                for (int q = 0; q < 8; q++) {
                    float4 vq = vp[q];
                    acc[q * 4 + 0] += wv * vq.x;
                    acc[q * 4 + 1] += wv * vq.y;
                    acc[q * 4 + 2] += wv * vq.z;
                    acc[q * 4 + 3] += wv * vq.w;
                }
            }

        float4* op = (float4*)&out[(((size_t)(b * HH + y) * WWI) + x) * DIM + h * HD];
        #pragma unroll
        for (int q = 0; q < 8; q++)
            op[q] = make_float4(acc[q*4], acc[q*4+1], acc[q*4+2], acc[q*4+3]);
    }
}

// ---------------------------------------------------------------------------
// Launch
// ---------------------------------------------------------------------------
extern "C" void kernel_launch(void* const* d_in, const int* in_sizes, int n_in,
                              void* d_out, int out_size) {
    const float* x    = (const float*)d_in[0];
    const float* fg   = (const float*)d_in[1];
    const float* bg   = (const float*)d_in[2];
    const float* w1   = (const float*)d_in[3];
    const float* w2   = (const float*)d_in[4];
    const float* w3   = (const float*)d_in[5];
    const float* w4   = (const float*)d_in[6];
    const float* bng  = (const float*)d_in[7];
    const float* bnb  = (const float*)d_in[8];
    const float* bnm  = (const float*)d_in[9];
    const float* bnv  = (const float*)d_in[10];
    const float* vw   = (const float*)d_in[11];
    const float* vb   = (const float*)d_in[12];
    const float* afgw = (const float*)d_in[13];
    const float* afgb = (const float*)d_in[14];
    const float* abgw = (const float*)d_in[15];
    const float* abgb = (const float*)d_in[16];
    const float* pw   = (const float*)d_in[17];
    const float* pb   = (const float*)d_in[18];
    float* out = (float*)d_out;

    float *xt, *b1, *b2, *vbuf, *pre, *attn;
    __nv_bfloat16 *c1h, *c1l, *Ph, *Pl, *Qh, *Ql, *wB1, *wB2, *wB3, *wB4;
    cudaGetSymbolAddress((void**)&xt,   g_xt);
    cudaGetSymbolAddress((void**)&b1,   g_b1);
    cudaGetSymbolAddress((void**)&b2,   g_b2);
    cudaGetSymbolAddress((void**)&vbuf, g_v);
    cudaGetSymbolAddress((void**)&pre,  g_pre);
    cudaGetSymbolAddress((void**)&attn, g_attn);
    cudaGetSymbolAddress((void**)&c1h,  g_c1h);
    cudaGetSymbolAddress((void**)&c1l,  g_c1l);
    cudaGetSymbolAddress((void**)&Ph,   g_Ph);
    cudaGetSymbolAddress((void**)&Pl,   g_Pl);
    cudaGetSymbolAddress((void**)&Qh,   g_Qh);
    cudaGetSymbolAddress((void**)&Ql,   g_Ql);
    cudaGetSymbolAddress((void**)&wB1,  g_wB1);
    cudaGetSymbolAddress((void**)&wB2,  g_wB2);
    cudaGetSymbolAddress((void**)&wB3,  g_wB3);
    cudaGetSymbolAddress((void**)&wB4,  g_wB4);

    cudaFuncSetAttribute(mma_conv<32, false, true>,
                         cudaFuncAttributeMaxDynamicSharedMemorySize, CONV_SMEM);
    cudaFuncSetAttribute(mma_conv<128, true, false>,
                         cudaFuncAttributeMaxDynamicSharedMemorySize, CONV_SMEM);
    cudaFuncSetAttribute(mma_conv<128, false, true>,
                         cudaFuncAttributeMaxDynamicSharedMemorySize, CONV_SMEM);

    const dim3 convGrid(HH, BATCH);
    const int smRows = NPIX * HEADS * 9;

    // weight prep (ldmatrix-ready split-bf16 layout)
    wprep_kernel<<<(2 * 9 * 128 * 16 + 255) / 256, 256>>>(w1, wB1, 32);
    wprep_kernel<<<(8 * 9 * 128 * 16 + 255) / 256, 256>>>(w2, wB2, 128);
    wprep_kernel<<<(8 * 9 * 128 * 16 + 255) / 256, 256>>>(w3, wB3, 128);
    wprep_kernel<<<(8 * 9 * 128 * 16 + 255) / 256, 256>>>(w4, wB4, 128);

    // input_cbt
    transpose_bat<<<dim3(L / 32, 1, BATCH), dim3(32, 8)>>>(x, xt, 32, L);
    split_kernel<<<(NPIX * 32 + 255) / 256, 256>>>(xt, c1h, c1l, NPIX * 32);
    mma_conv<32, false, true><<<convGrid, 256, CONV_SMEM>>>(
        c1h, c1l, wB1, bng, bnb, bnm, bnv, nullptr, Ph, Pl);
    mma_conv<128, true, false><<<convGrid, 256, CONV_SMEM>>>(
        Ph, Pl, wB2, bng + 128, bnb + 128, bnm + 128, bnv + 128, b2, nullptr, nullptr);

    // v projection
    linear_kernel<<<dim3(NPIX / 32, 1), 128>>>(b2, vw, vb, vbuf, 128);

    // fg attention pass
    transpose_bat<<<dim3(L / 32, 4, BATCH), dim3(32, 8)>>>(fg, b1, DIM, L);
    linear_kernel<<<dim3(NPIX / 32, 3), 128>>>(b1, afgw, afgb, attn, 324);
    softmax9_kernel<<<(smRows + 255) / 256, 256>>>(attn, smRows);
    apply_fold_kernel<<<dim3(WWI / 16, HH / 8, BATCH), 128>>>(attn, vbuf, pre);
    linear_kernel<<<dim3(NPIX / 32, 1), 128>>>(pre, pw, pb, b2, 128);   // xw_fg

    // bg attention pass (values = xw_fg)
    transpose_bat<<<dim3(L / 32, 4, BATCH), dim3(32, 8)>>>(bg, b1, DIM, L);
    linear_kernel<<<dim3(NPIX / 32, 3), 128>>>(b1, abgw, abgb, attn, 324);
    softmax9_kernel<<<(smRows + 255) / 256, 256>>>(attn, smRows);
    apply_fold_kernel<<<dim3(WWI / 16, HH / 8, BATCH), 128>>>(attn, b2, pre);
    linear_kernel<<<dim3(NPIX / 32, 1), 128>>>(pre, pw, pb, b1, 128);   // xw_bg

    // output_cbt
    split_kernel<<<(NPIX * 128 + 255) / 256, 256>>>(b1, Ph, Pl, NPIX * 128);
    mma_conv<128, false, true><<<convGrid, 256, CONV_SMEM>>>(
        Ph, Pl, wB3, bng + 256, bnb + 256, bnm + 256, bnv + 256, nullptr, Qh, Ql);
    mma_conv<128, true, false><<<convGrid, 256, CONV_SMEM>>>(
        Qh, Ql, wB4, bng + 384, bnb + 384, bnm + 384, bnv + 384, pre, nullptr, nullptr);

    // NHWC -> NCHW output
    transpose_bat<<<dim3(DIM / 32, L / 32, BATCH), dim3(32, 8)>>>(pre, out, L, DIM);
}